// round 3
// baseline (speedup 1.0000x reference)
#include <cuda_runtime.h>
#include <cuda_bf16.h>
#include <cstddef>

// Problem constants
#define S_DIM 64
#define B_DIM 4
#define N_DIM 256
#define D_MODEL 256
#define HEADS 8
#define DHEAD 32
#define INNER 256            // HEADS * DHEAD
#define QKV_COLS 768         // 3 * INNER
#define M_TOTAL (S_DIM * B_DIM * N_DIM)   // 65536
#define SCALE 0.17677669529663687f        // 32^-0.5

typedef unsigned long long ull;

// ---- packed f32x2 helpers (sm_103a FFMA2 path, PTX-only) ----
__device__ __forceinline__ ull fma2(ull a, ull b, ull c) {
    ull d;
    asm("fma.rn.f32x2 %0, %1, %2, %3;" : "=l"(d) : "l"(a), "l"(b), "l"(c));
    return d;
}
__device__ __forceinline__ ull add2(ull a, ull b) {
    ull d;
    asm("add.rn.f32x2 %0, %1, %2;" : "=l"(d) : "l"(a), "l"(b));
    return d;
}
__device__ __forceinline__ ull pack2(float lo, float hi) {
    ull d;
    asm("mov.b64 %0, {%1, %2};" : "=l"(d) : "f"(lo), "f"(hi));
    return d;
}
__device__ __forceinline__ float2 unpack2(ull v) {
    float lo, hi;
    asm("mov.b64 {%0, %1}, %2;" : "=f"(lo), "=f"(hi) : "l"(v));
    return make_float2(lo, hi);
}

// Scratch (allocation-free rule: __device__ globals)
__device__ float g_qkv[(size_t)M_TOTAL * QKV_COLS];   // 192 MB
__device__ float g_attn[(size_t)M_TOTAL * INNER];     // 64 MB

// ---------------------------------------------------------------------------
// SGEMM: C[M,N] = A[M,K] @ B[K,N] (+ bias). 128x128 block, 8x8 per thread,
// packed f32x2 FMAs, double-buffered SMEM tiles.
// ---------------------------------------------------------------------------
#define BM 128
#define BN 128
#define BK 16
#define TM 8
#define TN 8

__global__ __launch_bounds__(256, 2)
void sgemm_kernel(const float* __restrict__ A, const float* __restrict__ B,
                  const float* __restrict__ bias, float* __restrict__ C,
                  int M, int N, int K) {
    __shared__ float As[2][BK][BM];
    __shared__ float Bs[2][BK][BN];

    const int tid = threadIdx.x;
    const int bx = blockIdx.x;   // N tile
    const int by = blockIdx.y;   // M tile

    const int tcol = tid % (BN / TN);   // 0..15
    const int trow = tid / (BN / TN);   // 0..15

    const int arow  = tid / 4;          // 0..63
    const int acol4 = (tid % 4) * 4;    // 0,4,8,12
    const int brow  = tid / 32;         // 0..7
    const int bcol4 = (tid % 32) * 4;

    const float* Ab = A + (size_t)by * BM * K;
    const float* Bb = B + (size_t)bx * BN;

    ull accp[TM][TN / 2];
    #pragma unroll
    for (int i = 0; i < TM; i++)
        #pragma unroll
        for (int j = 0; j < TN / 2; j++) accp[i][j] = 0ull;

    // prologue: load tile 0 into buffer 0
    float4 pa[2], pb[2];
    #pragma unroll
    for (int r = 0; r < 2; r++) {
        pa[r] = *(const float4*)(Ab + (size_t)(arow + r * 64) * K + acol4);
        pb[r] = *(const float4*)(Bb + (size_t)(brow + r * 8) * N + bcol4);
    }
    #pragma unroll
    for (int r = 0; r < 2; r++) {
        int ar = arow + r * 64;
        As[0][acol4 + 0][ar] = pa[r].x;
        As[0][acol4 + 1][ar] = pa[r].y;
        As[0][acol4 + 2][ar] = pa[r].z;
        As[0][acol4 + 3][ar] = pa[r].w;
        *(float4*)&Bs[0][brow + r * 8][bcol4] = pb[r];
    }
    __syncthreads();

    const int nsteps = K / BK;
    int buf = 0;
    for (int step = 0; step < nsteps; step++) {
        // prefetch next tile (GMEM -> regs) while computing current
        if (step + 1 < nsteps) {
            int kk = (step + 1) * BK;
            #pragma unroll
            for (int r = 0; r < 2; r++) {
                pa[r] = *(const float4*)(Ab + (size_t)(arow + r * 64) * K + kk + acol4);
                pb[r] = *(const float4*)(Bb + (size_t)(kk + brow + r * 8) * N + bcol4);
            }
        }

        #pragma unroll
        for (int k = 0; k < BK; k++) {
            float4 a0 = *(const float4*)&As[buf][k][trow * TM];
            float4 a1 = *(const float4*)&As[buf][k][trow * TM + 4];
            ulonglong2 b0 = *(const ulonglong2*)&Bs[buf][k][tcol * TN];
            ulonglong2 b1 = *(const ulonglong2*)&Bs[buf][k][tcol * TN + 4];
            ull rb[4] = {b0.x, b0.y, b1.x, b1.y};
            float ra[TM] = {a0.x, a0.y, a0.z, a0.w, a1.x, a1.y, a1.z, a1.w};
            #pragma unroll
            for (int i = 0; i < TM; i++) {
                ull rap = pack2(ra[i], ra[i]);
                #pragma unroll
                for (int jp = 0; jp < TN / 2; jp++)
                    accp[i][jp] = fma2(rap, rb[jp], accp[i][jp]);
            }
        }

        if (step + 1 < nsteps) {
            int nb = buf ^ 1;
            #pragma unroll
            for (int r = 0; r < 2; r++) {
                int ar = arow + r * 64;
                As[nb][acol4 + 0][ar] = pa[r].x;
                As[nb][acol4 + 1][ar] = pa[r].y;
                As[nb][acol4 + 2][ar] = pa[r].z;
                As[nb][acol4 + 3][ar] = pa[r].w;
                *(float4*)&Bs[nb][brow + r * 8][bcol4] = pb[r];
            }
            __syncthreads();
            buf = nb;
        }
    }

    // Epilogue
    #pragma unroll
    for (int i = 0; i < TM; i++) {
        size_t row = (size_t)by * BM + trow * TM + i;
        float* Cp = C + row * N + (size_t)bx * BN + tcol * TN;
        #pragma unroll
        for (int jq = 0; jq < 2; jq++) {
            float2 u0 = unpack2(accp[i][2 * jq + 0]);
            float2 u1 = unpack2(accp[i][2 * jq + 1]);
            float4 v = make_float4(u0.x, u0.y, u1.x, u1.y);
            if (bias) {
                const float* bp = bias + (size_t)bx * BN + tcol * TN + jq * 4;
                v.x += bp[0]; v.y += bp[1]; v.z += bp[2]; v.w += bp[3];
            }
            *(float4*)(Cp + jq * 4) = v;
        }
    }
}

// ---------------------------------------------------------------------------
// Attention: one block of 256 threads per (s, b, h); thread i = query row i.
// q loaded straight from GMEM (no smem), K/V in smem (broadcast reads),
// mask bit-packed. No-max softmax, 4-way j batching for ILP, f32x2 FMAs.
// smem = 32K (K) + 32K (V) + 8K (mask) = 72 KB -> 2 CTAs/SM, 4 warps/SMSP.
// ---------------------------------------------------------------------------
#define ATTN_SMEM_BYTES ((256 * 32 + 256 * 32) * 4 + 2048 * 4)

__global__ __launch_bounds__(256, 2)
void attn_kernel(const float* __restrict__ qkv, const int* __restrict__ mask,
                 float* __restrict__ outp) {
    extern __shared__ float sm[];
    float* sm_k = sm;                         // [256][32]
    float* sm_v = sm_k + 256 * 32;            // [256][32]
    unsigned* sm_m = (unsigned*)(sm_v + 256 * 32);  // [256][8] bit-packed

    const int tid = threadIdx.x;
    const int h = blockIdx.x;
    const int b = blockIdx.y;
    const int s = blockIdx.z;

    const size_t base = ((size_t)(s * B_DIM + b) * N_DIM) * QKV_COLS;
    const int qoff = h * DHEAD;
    const int koff = INNER + h * DHEAD;
    const int voff = 2 * INNER + h * DHEAD;

    // cooperative load k/v tiles (float4, coalesced per-row)
    for (int idx = tid; idx < 256 * 8; idx += 256) {
        int j  = idx >> 3;
        int d4 = (idx & 7) * 4;
        const float* rowp = qkv + base + (size_t)j * QKV_COLS;
        *(float4*)&sm_k[j * 32 + d4] = *(const float4*)(rowp + koff + d4);
        *(float4*)&sm_v[j * 32 + d4] = *(const float4*)(rowp + voff + d4);
    }

    // bit-pack mask[s]
    const int* mrow = mask + (size_t)s * N_DIM * N_DIM;
    for (int w = tid; w < 2048; w += 256) {
        int i = w >> 3, c = w & 7;
        const int* p = mrow + i * N_DIM + c * 32;
        unsigned bits = 0;
        #pragma unroll 8
        for (int bb = 0; bb < 32; bb++) bits |= (unsigned)(p[bb] != 0) << bb;
        sm_m[w] = bits;
    }

    // q row from GMEM, pre-scaled, packed (overlaps with smem fills)
    const int i = tid;
    ull qp[16];
    {
        const float* qrow = qkv + base + (size_t)i * QKV_COLS + qoff;
        #pragma unroll
        for (int d4 = 0; d4 < 8; d4++) {
            float4 t = *(const float4*)(qrow + d4 * 4);
            qp[2 * d4 + 0] = pack2(t.x * SCALE, t.y * SCALE);
            qp[2 * d4 + 1] = pack2(t.z * SCALE, t.w * SCALE);
        }
    }
    __syncthreads();

    ull acc[16];
    #pragma unroll
    for (int d = 0; d < 16; d++) acc[d] = 0ull;
    float lsum = 0.0f;

    for (int jw = 0; jw < 8; jw++) {
        const unsigned mb = sm_m[i * 8 + jw];
        #pragma unroll
        for (int g = 0; g < 8; g++) {
            const int j0 = jw * 32 + g * 4;

            // ---- 4 independent score dots (8 fma2 chains) ----
            ull sa[4][2];
            #pragma unroll
            for (int jj = 0; jj < 4; jj++) { sa[jj][0] = 0ull; sa[jj][1] = 0ull; }
            #pragma unroll
            for (int d = 0; d < 8; d++) {
                #pragma unroll
                for (int jj = 0; jj < 4; jj++) {
                    ulonglong2 kk = ((const ulonglong2*)&sm_k[(j0 + jj) * 32])[d];
                    sa[jj][0] = fma2(qp[2 * d + 0], kk.x, sa[jj][0]);
                    sa[jj][1] = fma2(qp[2 * d + 1], kk.y, sa[jj][1]);
                }
            }

            // ---- 4 exps ----
            float p[4];
            #pragma unroll
            for (int jj = 0; jj < 4; jj++) {
                float2 r = unpack2(add2(sa[jj][0], sa[jj][1]));
                float sc = r.x + r.y;
                p[jj] = ((mb >> (g * 4 + jj)) & 1u) ? __expf(sc) : 0.0f;
            }
            lsum += (p[0] + p[1]) + (p[2] + p[3]);

            ull pp[4];
            #pragma unroll
            for (int jj = 0; jj < 4; jj++) pp[jj] = pack2(p[jj], p[jj]);

            // ---- PV accumulate, 4-way ILP per d ----
            #pragma unroll
            for (int d = 0; d < 8; d++) {
                ull t0 = acc[2 * d + 0];
                ull t1 = acc[2 * d + 1];
                #pragma unroll
                for (int jj = 0; jj < 4; jj++) {
                    ulonglong2 vv = ((const ulonglong2*)&sm_v[(j0 + jj) * 32])[d];
                    t0 = fma2(pp[jj], vv.x, t0);
                    t1 = fma2(pp[jj], vv.y, t1);
                }
                acc[2 * d + 0] = t0;
                acc[2 * d + 1] = t1;
            }
        }
    }

    const float inv = 1.0f / lsum;
    const size_t orow = ((size_t)(s * B_DIM + b) * N_DIM + i) * INNER + h * DHEAD;
    #pragma unroll
    for (int d = 0; d < 8; d++) {
        float2 u0 = unpack2(acc[2 * d + 0]);
        float2 u1 = unpack2(acc[2 * d + 1]);
        *(float4*)(outp + orow + d * 4) =
            make_float4(u0.x * inv, u0.y * inv, u1.x * inv, u1.y * inv);
    }
}

// ---------------------------------------------------------------------------
// Launch
// ---------------------------------------------------------------------------
extern "C" void kernel_launch(void* const* d_in, const int* in_sizes, int n_in,
                              void* d_out, int out_size) {
    const float* x     = (const float*)d_in[0];
    const int*   mask  = (const int*)d_in[1];
    const float* Wqkv  = (const float*)d_in[2];
    const float* Wout  = (const float*)d_in[3];
    const float* bout  = (const float*)d_in[4];
    float* out = (float*)d_out;

    float* qkvbuf = nullptr;
    float* attnbuf = nullptr;
    cudaGetSymbolAddress((void**)&qkvbuf, g_qkv);
    cudaGetSymbolAddress((void**)&attnbuf, g_attn);

    cudaFuncSetAttribute(attn_kernel, cudaFuncAttributeMaxDynamicSharedMemorySize,
                         ATTN_SMEM_BYTES);

    // 1) QKV projection: [65536,256] @ [256,768]
    {
        dim3 grid(QKV_COLS / BN, M_TOTAL / BM);
        sgemm_kernel<<<grid, 256>>>(x, Wqkv, nullptr, qkvbuf,
                                    M_TOTAL, QKV_COLS, D_MODEL);
    }
    // 2) Attention per (s,b,h)
    {
        dim3 grid(HEADS, B_DIM, S_DIM);
        attn_kernel<<<grid, 256, ATTN_SMEM_BYTES>>>(qkvbuf, mask, attnbuf);
    }
    // 3) Output projection: [65536,256] @ [256,256] + bias
    {
        dim3 grid(INNER / BN, M_TOTAL / BM);
        sgemm_kernel<<<grid, 256>>>(attnbuf, Wout, bout, out,
                                    M_TOTAL, D_MODEL, INNER);
    }
}

// round 5
// speedup vs baseline: 1.3808x; 1.3808x over previous
#include <cuda_runtime.h>
#include <cuda_bf16.h>
#include <cstddef>

// Problem constants
#define S_DIM 64
#define B_DIM 4
#define N_DIM 256
#define D_MODEL 256
#define HEADS 8
#define DHEAD 32
#define INNER 256            // HEADS * DIM_HEAD
#define QKV_COLS 768         // 3 * INNER
#define M_TOTAL (S_DIM * B_DIM * N_DIM)   // 65536
#define SCALE 0.17677669529663687f        // 32^-0.5

typedef unsigned long long ull;

// ---- packed f32x2 helpers (sm_103a FFMA2 path, PTX-only) ----
__device__ __forceinline__ ull fma2(ull a, ull b, ull c) {
    ull d;
    asm("fma.rn.f32x2 %0, %1, %2, %3;" : "=l"(d) : "l"(a), "l"(b), "l"(c));
    return d;
}
__device__ __forceinline__ ull add2(ull a, ull b) {
    ull d;
    asm("add.rn.f32x2 %0, %1, %2;" : "=l"(d) : "l"(a), "l"(b));
    return d;
}
__device__ __forceinline__ ull pack2(float lo, float hi) {
    ull d;
    asm("mov.b64 %0, {%1, %2};" : "=l"(d) : "f"(lo), "f"(hi));
    return d;
}
__device__ __forceinline__ float2 unpack2(ull v) {
    float lo, hi;
    asm("mov.b64 {%0, %1}, %2;" : "=f"(lo), "=f"(hi) : "l"(v));
    return make_float2(lo, hi);
}

// Scratch (allocation-free rule: __device__ globals)
__device__ float g_qkv[(size_t)M_TOTAL * QKV_COLS];   // 192 MB
__device__ float g_attn[(size_t)M_TOTAL * INNER];     // 64 MB
__device__ unsigned g_maskpack[S_DIM][N_DIM][8];      // bit-packed mask per s

// ---------------------------------------------------------------------------
// Mask pre-pack: one block per s, thread i packs row i (8 words of 32 bits).
// ---------------------------------------------------------------------------
__global__ void pack_mask_kernel(const int* __restrict__ mask) {
    const int s = blockIdx.x;
    const int i = threadIdx.x;
    const int* p = mask + ((size_t)s * N_DIM + i) * N_DIM;
    #pragma unroll
    for (int c = 0; c < 8; c++) {
        unsigned bits = 0;
        #pragma unroll 8
        for (int bb = 0; bb < 32; bb++)
            bits |= (unsigned)(p[c * 32 + bb] != 0) << bb;
        g_maskpack[s][i][c] = bits;
    }
}

// ---------------------------------------------------------------------------
// SGEMM: C[M,N] = A[M,K] @ B[K,N] (+ bias). 128x128 block, 8x8 per thread,
// packed f32x2 FMAs. (R2 version — measured best.)
// ---------------------------------------------------------------------------
#define BM 128
#define BN 128
#define BK 16
#define TM 8
#define TN 8

__global__ __launch_bounds__(256, 2)
void sgemm_kernel(const float* __restrict__ A, const float* __restrict__ B,
                  const float* __restrict__ bias, float* __restrict__ C,
                  int M, int N, int K) {
    __shared__ float As[BK][BM];
    __shared__ float Bs[BK][BN];

    const int tid = threadIdx.x;
    const int bx = blockIdx.x;   // N tile
    const int by = blockIdx.y;   // M tile

    const int tcol = tid % (BN / TN);   // 0..15
    const int trow = tid / (BN / TN);   // 0..15

    const int arow  = tid / 4;          // 0..63
    const int acol4 = (tid % 4) * 4;    // 0,4,8,12
    const int brow  = tid / 32;         // 0..7
    const int bcol4 = (tid % 32) * 4;

    const float* Ab = A + (size_t)by * BM * K;
    const float* Bb = B + (size_t)bx * BN;

    ull accp[TM][TN / 2];
    #pragma unroll
    for (int i = 0; i < TM; i++)
        #pragma unroll
        for (int j = 0; j < TN / 2; j++) accp[i][j] = 0ull;

    for (int kk = 0; kk < K; kk += BK) {
        #pragma unroll
        for (int r = 0; r < 2; r++) {
            int ar = arow + r * 64;
            float4 v = *(const float4*)(Ab + (size_t)ar * K + kk + acol4);
            As[acol4 + 0][ar] = v.x;
            As[acol4 + 1][ar] = v.y;
            As[acol4 + 2][ar] = v.z;
            As[acol4 + 3][ar] = v.w;
        }
        #pragma unroll
        for (int r = 0; r < 2; r++) {
            int br = brow + r * 8;
            *(float4*)&Bs[br][bcol4] =
                *(const float4*)(Bb + (size_t)(kk + br) * N + bcol4);
        }
        __syncthreads();

        #pragma unroll
        for (int k = 0; k < BK; k++) {
            float4 a0 = *(const float4*)&As[k][trow * TM];
            float4 a1 = *(const float4*)&As[k][trow * TM + 4];
            ulonglong2 b0 = *(const ulonglong2*)&Bs[k][tcol * TN];
            ulonglong2 b1 = *(const ulonglong2*)&Bs[k][tcol * TN + 4];
            ull rb[4] = {b0.x, b0.y, b1.x, b1.y};
            float ra[TM] = {a0.x, a0.y, a0.z, a0.w, a1.x, a1.y, a1.z, a1.w};
            #pragma unroll
            for (int i = 0; i < TM; i++) {
                ull rap = pack2(ra[i], ra[i]);
                #pragma unroll
                for (int jp = 0; jp < TN / 2; jp++)
                    accp[i][jp] = fma2(rap, rb[jp], accp[i][jp]);
            }
        }
        __syncthreads();
    }

    // Epilogue
    #pragma unroll
    for (int i = 0; i < TM; i++) {
        size_t row = (size_t)by * BM + trow * TM + i;
        float* Cp = C + row * N + (size_t)bx * BN + tcol * TN;
        #pragma unroll
        for (int jq = 0; jq < 2; jq++) {
            float2 u0 = unpack2(accp[i][2 * jq + 0]);
            float2 u1 = unpack2(accp[i][2 * jq + 1]);
            float4 v = make_float4(u0.x, u0.y, u1.x, u1.y);
            if (bias) {
                const float* bp = bias + (size_t)bx * BN + tcol * TN + jq * 4;
                v.x += bp[0]; v.y += bp[1]; v.z += bp[2]; v.w += bp[3];
            }
            *(float4*)(Cp + jq * 4) = v;
        }
    }
}

// ---------------------------------------------------------------------------
// Attention: one block of 128 threads per (s, b, h); thread t owns query
// rows t and t+128 (K/V LDS amortized over 2 rows). No-max softmax
// (scores are O(1); masked -> p=0), packed f32x2 FMAs.
// smem = K 32KB + V 32KB = 64 KB -> 2 CTAs/SM -> 2 warps/SMSP.
// q read directly from GMEM; mask read pre-packed from GMEM.
// ---------------------------------------------------------------------------
#define ATTN_SMEM_BYTES ((256 * 32 + 256 * 32) * 4)

__global__ __launch_bounds__(128, 2)
void attn_kernel(const float* __restrict__ qkv, float* __restrict__ outp) {
    extern __shared__ float sm[];
    float* sm_k = sm;                  // [256][32]
    float* sm_v = sm_k + 256 * 32;     // [256][32]

    const int tid = threadIdx.x;
    const int h = blockIdx.x;
    const int b = blockIdx.y;
    const int s = blockIdx.z;

    const size_t base = ((size_t)(s * B_DIM + b) * N_DIM) * QKV_COLS;
    const int qoff = h * DHEAD;
    const int koff = INNER + h * DHEAD;
    const int voff = 2 * INNER + h * DHEAD;

    // cooperative load k/v tiles (float4, coalesced per-row)
    for (int idx = tid; idx < 256 * 8; idx += 128) {
        int j  = idx >> 3;
        int d4 = (idx & 7) * 4;
        const float* rowp = qkv + base + (size_t)j * QKV_COLS;
        *(float4*)&sm_k[j * 32 + d4] = *(const float4*)(rowp + koff + d4);
        *(float4*)&sm_v[j * 32 + d4] = *(const float4*)(rowp + voff + d4);
    }

    const int i0 = tid;
    const int i1 = tid + 128;

    // q rows straight from GMEM, pre-scaled, packed into f32 pairs
    ull q0p[16], q1p[16];
    {
        const float* q0 = qkv + base + (size_t)i0 * QKV_COLS + qoff;
        const float* q1 = qkv + base + (size_t)i1 * QKV_COLS + qoff;
        #pragma unroll
        for (int d4 = 0; d4 < 8; d4++) {
            float4 t0 = *(const float4*)(q0 + d4 * 4);
            float4 t1 = *(const float4*)(q1 + d4 * 4);
            q0p[2 * d4 + 0] = pack2(t0.x * SCALE, t0.y * SCALE);
            q0p[2 * d4 + 1] = pack2(t0.z * SCALE, t0.w * SCALE);
            q1p[2 * d4 + 0] = pack2(t1.x * SCALE, t1.y * SCALE);
            q1p[2 * d4 + 1] = pack2(t1.z * SCALE, t1.w * SCALE);
        }
    }
    __syncthreads();

    ull acc0[16], acc1[16];
    #pragma unroll
    for (int d = 0; d < 16; d++) { acc0[d] = 0ull; acc1[d] = 0ull; }
    float l0 = 0.0f, l1 = 0.0f;

    for (int jw = 0; jw < 8; jw++) {
        const unsigned mb0 = g_maskpack[s][i0][jw];
        const unsigned mb1 = g_maskpack[s][i1][jw];
        #pragma unroll 2
        for (int jj = 0; jj < 32; jj++) {
            const int j = jw * 32 + jj;
            const ulonglong2* kp = (const ulonglong2*)&sm_k[j * 32];
            ull a0[4] = {0ull, 0ull, 0ull, 0ull};
            ull a1[4] = {0ull, 0ull, 0ull, 0ull};
            #pragma unroll
            for (int d = 0; d < 8; d++) {
                ulonglong2 kk = kp[d];
                a0[(2 * d + 0) & 3] = fma2(q0p[2 * d + 0], kk.x, a0[(2 * d + 0) & 3]);
                a0[(2 * d + 1) & 3] = fma2(q0p[2 * d + 1], kk.y, a0[(2 * d + 1) & 3]);
                a1[(2 * d + 0) & 3] = fma2(q1p[2 * d + 0], kk.x, a1[(2 * d + 0) & 3]);
                a1[(2 * d + 1) & 3] = fma2(q1p[2 * d + 1], kk.y, a1[(2 * d + 1) & 3]);
            }
            float2 r0 = unpack2(add2(add2(a0[0], a0[1]), add2(a0[2], a0[3])));
            float2 r1 = unpack2(add2(add2(a1[0], a1[1]), add2(a1[2], a1[3])));
            float sc0 = r0.x + r0.y;
            float sc1 = r1.x + r1.y;

            float p0 = ((mb0 >> jj) & 1u) ? __expf(sc0) : 0.0f;
            float p1 = ((mb1 >> jj) & 1u) ? __expf(sc1) : 0.0f;
            l0 += p0;
            l1 += p1;
            ull pp0 = pack2(p0, p0);
            ull pp1 = pack2(p1, p1);

            const ulonglong2* vp = (const ulonglong2*)&sm_v[j * 32];
            #pragma unroll
            for (int d = 0; d < 8; d++) {
                ulonglong2 vv = vp[d];
                acc0[2 * d + 0] = fma2(pp0, vv.x, acc0[2 * d + 0]);
                acc0[2 * d + 1] = fma2(pp0, vv.y, acc0[2 * d + 1]);
                acc1[2 * d + 0] = fma2(pp1, vv.x, acc1[2 * d + 0]);
                acc1[2 * d + 1] = fma2(pp1, vv.y, acc1[2 * d + 1]);
            }
        }
    }

    const float inv0 = 1.0f / l0;
    const float inv1 = 1.0f / l1;
    const size_t orow0 = ((size_t)(s * B_DIM + b) * N_DIM + i0) * INNER + h * DHEAD;
    const size_t orow1 = ((size_t)(s * B_DIM + b) * N_DIM + i1) * INNER + h * DHEAD;
    #pragma unroll
    for (int d = 0; d < 8; d++) {
        float2 u0 = unpack2(acc0[2 * d + 0]);
        float2 u1 = unpack2(acc0[2 * d + 1]);
        *(float4*)(outp + orow0 + d * 4) =
            make_float4(u0.x * inv0, u0.y * inv0, u1.x * inv0, u1.y * inv0);
        float2 w0 = unpack2(acc1[2 * d + 0]);
        float2 w1 = unpack2(acc1[2 * d + 1]);
        *(float4*)(outp + orow1 + d * 4) =
            make_float4(w0.x * inv1, w0.y * inv1, w1.x * inv1, w1.y * inv1);
    }
}

// ---------------------------------------------------------------------------
// Launch
// ---------------------------------------------------------------------------
extern "C" void kernel_launch(void* const* d_in, const int* in_sizes, int n_in,
                              void* d_out, int out_size) {
    const float* x     = (const float*)d_in[0];
    const int*   mask  = (const int*)d_in[1];
    const float* Wqkv  = (const float*)d_in[2];
    const float* Wout  = (const float*)d_in[3];
    const float* bout  = (const float*)d_in[4];
    float* out = (float*)d_out;

    float* qkvbuf = nullptr;
    float* attnbuf = nullptr;
    cudaGetSymbolAddress((void**)&qkvbuf, g_qkv);
    cudaGetSymbolAddress((void**)&attnbuf, g_attn);

    cudaFuncSetAttribute(attn_kernel, cudaFuncAttributeMaxDynamicSharedMemorySize,
                         ATTN_SMEM_BYTES);

    // 0) Pre-pack mask bits (depends only on s; 64 tiny blocks)
    pack_mask_kernel<<<S_DIM, N_DIM>>>(mask);

    // 1) QKV projection: [65536,256] @ [256,768]
    {
        dim3 grid(QKV_COLS / BN, M_TOTAL / BM);
        sgemm_kernel<<<grid, 256>>>(x, Wqkv, nullptr, qkvbuf,
                                    M_TOTAL, QKV_COLS, D_MODEL);
    }
    // 2) Attention per (s,b,h): 128 threads, 2 query rows/thread
    {
        dim3 grid(HEADS, B_DIM, S_DIM);
        attn_kernel<<<grid, 128, ATTN_SMEM_BYTES>>>(qkvbuf, attnbuf);
    }
    // 3) Output projection: [65536,256] @ [256,256] + bias
    {
        dim3 grid(INNER / BN, M_TOTAL / BM);
        sgemm_kernel<<<grid, 256>>>(attnbuf, Wout, bout, out,
                                    M_TOTAL, D_MODEL, INNER);
    }
}